// round 8
// baseline (speedup 1.0000x reference)
#include <cuda_runtime.h>
#include <math.h>
#include <stdint.h>

// ---------------- static scratch (no allocations allowed) ----------------
#define MAXN 100000
#define MAXB 4096
#define MAXE 3200000

static __device__ float g_hw  [MAXN * 128];
static __device__ float g_res [MAXN * 128];
static __device__ float g_h   [MAXN * 128];
static __device__ float g_on  [MAXN];
static __device__ float g_in  [MAXN];
static __device__ float g_aw  [MAXN];
static __device__ int   g_degs[MAXN];
static __device__ int   g_degd[MAXN];
static __device__ int   g_rowptr[MAXN + 1];
static __device__ int   g_cursor[MAXN];
static __device__ int   g_csrc[MAXE];
static __device__ int   g_gcnt[MAXB];
static __device__ int   g_gptr[MAXB + 1];
static __device__ int   g_bsums[256];
static __device__ float g_gf  [MAXB * 256];
static __device__ float g_z   [MAXB * 128];
static __device__ float g_gcat[MAXB * 832];

#define BN_INV 0.99999500003749971f

// ---------------- init / degree kernels ----------------
__global__ void k_init(int* degs, int* degd, int* gcnt, int N, int B) {
    int i = blockIdx.x * blockDim.x + threadIdx.x;
    if (i < N) { degs[i] = 0; degd[i] = 0; }
    if (i < B) gcnt[i] = 0;
}
__global__ void k_copy_i(const int* __restrict__ s, int* __restrict__ d, int n) {
    int i = blockIdx.x * blockDim.x + threadIdx.x;
    if (i < n) d[i] = s[i];
}
__global__ void k_count(const int* __restrict__ src, const int* __restrict__ dst,
                        int E, int* ds, int* dd) {
    int i = blockIdx.x * blockDim.x + threadIdx.x;
    if (i < E) {
        atomicAdd(&ds[src[i]], 1);
        atomicAdd(&dd[dst[i]], 1);
    }
}
__global__ void k_hist(const int* __restrict__ gid, int N, int* cnt) {
    int i = blockIdx.x * blockDim.x + threadIdx.x;
    if (i < N) atomicAdd(&cnt[gid[i]], 1);
}
__global__ void k_norm(const int* __restrict__ ds, const int* __restrict__ dd,
                       float* on, float* inn, int N) {
    int i = blockIdx.x * blockDim.x + threadIdx.x;
    if (i < N) {
        on[i]  = rsqrtf((float)max(ds[i], 1));
        inn[i] = rsqrtf((float)max(dd[i], 1));
    }
}

// ---------------- exclusive scan (3-phase, n <= 128*1024) ----------------
__global__ void k_scan_partial(const int* __restrict__ cnt, int* __restrict__ out,
                               int* __restrict__ bsums, int n) {
    __shared__ int sh[8];
    int base = blockIdx.x * 1024;
    int t = threadIdx.x;           // 256 threads, 4 elems each
    int idx = base + t * 4;
    int v[4], s = 0;
#pragma unroll
    for (int j = 0; j < 4; j++) {
        v[j] = (idx + j < n) ? cnt[idx + j] : 0;
        s += v[j];
    }
    int lane = t & 31, wid = t >> 5;
    int x = s;
#pragma unroll
    for (int o = 1; o < 32; o <<= 1) {
        int y = __shfl_up_sync(0xffffffffu, x, o);
        if (lane >= o) x += y;
    }
    if (lane == 31) sh[wid] = x;
    __syncthreads();
    if (wid == 0 && lane < 8) {
        int w = sh[lane];
#pragma unroll
        for (int o = 1; o < 8; o <<= 1) {
            int y = __shfl_up_sync(0xffu, w, o);
            if (lane >= o) w += y;
        }
        sh[lane] = w;
    }
    __syncthreads();
    int run = (x - s) + (wid > 0 ? sh[wid - 1] : 0);
#pragma unroll
    for (int j = 0; j < 4; j++) {
        if (idx + j < n) out[idx + j] = run;
        run += v[j];
    }
    if (t == 255) bsums[blockIdx.x] = run;   // block total
}
__global__ void k_scan_bsums(int* bsums, int nb) {   // nb <= 128; 128 threads
    __shared__ int sh[4];
    int t = threadIdx.x;
    int v = (t < nb) ? bsums[t] : 0;
    int lane = t & 31, wid = t >> 5;
    int x = v;
#pragma unroll
    for (int o = 1; o < 32; o <<= 1) {
        int y = __shfl_up_sync(0xffffffffu, x, o);
        if (lane >= o) x += y;
    }
    if (lane == 31) sh[wid] = x;
    __syncthreads();
    if (wid == 0 && lane < 4) {
        int w = sh[lane];
#pragma unroll
        for (int o = 1; o < 4; o <<= 1) {
            int y = __shfl_up_sync(0xfu, w, o);
            if (lane >= o) w += y;
        }
        sh[lane] = w;
    }
    __syncthreads();
    int excl = (x - v) + (wid > 0 ? sh[wid - 1] : 0);
    if (t < nb) bsums[t] = excl;
}
__global__ void k_scan_add(int* out, const int* __restrict__ bsums, int n, int total) {
    int i = blockIdx.x * blockDim.x + threadIdx.x;
    if (i < n) out[i] += bsums[i >> 10];
    if (i == 0) out[n] = total;
}

__global__ void k_fill_csr(const int* __restrict__ src, const int* __restrict__ dst,
                           int E, int* cursor, int* __restrict__ csrc) {
    int i = blockIdx.x * blockDim.x + threadIdx.x;
    if (i < E) {
        int p = atomicAdd(&cursor[dst[i]], 1);
        csrc[p] = src[i];
    }
}

// ---------------- node GEMM: C[M,128] = epi(A[M,128](*row scale) @ W[128,128] (+bias)) ----------------
// BM=128, BN=128, BK=16; 256 threads (16x16), 8x8 per thread.
__global__ void __launch_bounds__(256, 2)
k_gemm_node(const float* __restrict__ A, const float* __restrict__ W,
            const float* __restrict__ scale, const float* __restrict__ bias,
            float* __restrict__ C, int M, int do_relu) {
    __shared__ float As[16][132];   // [k][m]
    __shared__ float Ws[16][128];   // [k][n]
    int t  = threadIdx.x;
    int tx = t & 15, ty = t >> 4;
    int row0 = blockIdx.x * 128;

    float acc[8][8];
#pragma unroll
    for (int j = 0; j < 8; j++)
#pragma unroll
        for (int i = 0; i < 8; i++) acc[j][i] = 0.0f;

    for (int kt = 0; kt < 8; kt++) {
#pragma unroll
        for (int i = 0; i < 2; i++) {
            int f = t + i * 256;          // 0..511
            int r = f >> 2, c4 = f & 3;   // r: 0..127, c4: 0..3
            int grow = row0 + r;
            float4 v = make_float4(0.f, 0.f, 0.f, 0.f);
            if (grow < M) {
                v = *reinterpret_cast<const float4*>(&A[(size_t)grow * 128 + kt * 16 + c4 * 4]);
                if (scale) {
                    float s = scale[grow];
                    v.x *= s; v.y *= s; v.z *= s; v.w *= s;
                }
            }
            As[c4 * 4 + 0][r] = v.x;
            As[c4 * 4 + 1][r] = v.y;
            As[c4 * 4 + 2][r] = v.z;
            As[c4 * 4 + 3][r] = v.w;
        }
#pragma unroll
        for (int i = 0; i < 2; i++) {
            int f = t + i * 256;
            int r = f >> 5, c4 = f & 31;  // r: 0..15, c4: 0..31
            *reinterpret_cast<float4*>(&Ws[r][c4 * 4]) =
                *reinterpret_cast<const float4*>(&W[(size_t)(kt * 16 + r) * 128 + c4 * 4]);
        }
        __syncthreads();
#pragma unroll
        for (int k = 0; k < 16; k++) {
            float4 A0 = *reinterpret_cast<float4*>(&As[k][ty * 4]);
            float4 A1 = *reinterpret_cast<float4*>(&As[k][ty * 4 + 64]);
            float4 B0 = *reinterpret_cast<float4*>(&Ws[k][tx * 4]);
            float4 B1 = *reinterpret_cast<float4*>(&Ws[k][tx * 4 + 64]);
            float am[8] = {A0.x, A0.y, A0.z, A0.w, A1.x, A1.y, A1.z, A1.w};
            float bn[8] = {B0.x, B0.y, B0.z, B0.w, B1.x, B1.y, B1.z, B1.w};
#pragma unroll
            for (int j = 0; j < 8; j++)
#pragma unroll
                for (int i = 0; i < 8; i++)
                    acc[j][i] = fmaf(am[j], bn[i], acc[j][i]);
        }
        __syncthreads();
    }

#pragma unroll
    for (int j = 0; j < 8; j++) {
        int row = row0 + ((j < 4) ? (ty * 4 + j) : (64 + ty * 4 + j - 4));
        if (row >= M) continue;
#pragma unroll
        for (int half = 0; half < 2; half++) {
            int c0 = (half == 0) ? tx * 4 : 64 + tx * 4;
            float o[4];
#pragma unroll
            for (int i = 0; i < 4; i++) {
                float v = acc[j][half * 4 + i];
                if (bias) v += bias[c0 + i];
                if (do_relu) v = fmaxf(v, 0.0f);
                o[i] = v;
            }
            *reinterpret_cast<float4*>(&C[(size_t)row * 128 + c0]) =
                make_float4(o[0], o[1], o[2], o[3]);
        }
    }
}

// ---------------- CSR gather + finalize (+ optional atom-weight sigmoid) ----------------
// one warp per dst node; lane owns a float4 (4 columns)
__global__ void k_gather(const float* __restrict__ hw, const int* __restrict__ rowptr,
                         const int* __restrict__ csrc, const float* __restrict__ inn,
                         const float* __restrict__ bias, const float* __restrict__ res,
                         float* __restrict__ hout, float* __restrict__ aw,
                         const float* __restrict__ awW, const float* __restrict__ awb, int N) {
    int node = (blockIdx.x * blockDim.x + threadIdx.x) >> 5;
    int lane = threadIdx.x & 31;
    if (node >= N) return;
    int e = __ldg(&rowptr[node]), end = __ldg(&rowptr[node + 1]);
    const float4* hw4 = reinterpret_cast<const float4*>(hw);
    float4 a0 = make_float4(0.f, 0.f, 0.f, 0.f), a1 = a0, a2 = a0, a3 = a0;
    for (; e + 4 <= end; e += 4) {
        int s0 = __ldg(&csrc[e]);
        int s1 = __ldg(&csrc[e + 1]);
        int s2 = __ldg(&csrc[e + 2]);
        int s3 = __ldg(&csrc[e + 3]);
        float4 v0 = __ldg(hw4 + (size_t)s0 * 32 + lane);
        float4 v1 = __ldg(hw4 + (size_t)s1 * 32 + lane);
        float4 v2 = __ldg(hw4 + (size_t)s2 * 32 + lane);
        float4 v3 = __ldg(hw4 + (size_t)s3 * 32 + lane);
        a0.x += v0.x; a0.y += v0.y; a0.z += v0.z; a0.w += v0.w;
        a1.x += v1.x; a1.y += v1.y; a1.z += v1.z; a1.w += v1.w;
        a2.x += v2.x; a2.y += v2.y; a2.z += v2.z; a2.w += v2.w;
        a3.x += v3.x; a3.y += v3.y; a3.z += v3.z; a3.w += v3.w;
    }
    for (; e < end; e++) {
        int s = __ldg(&csrc[e]);
        float4 v = __ldg(hw4 + (size_t)s * 32 + lane);
        a0.x += v.x; a0.y += v.y; a0.z += v.z; a0.w += v.w;
    }
    float4 acc = make_float4(a0.x + a1.x + a2.x + a3.x,
                             a0.y + a1.y + a2.y + a3.y,
                             a0.z + a1.z + a2.z + a3.z,
                             a0.w + a1.w + a2.w + a3.w);
    float sc = __ldg(&inn[node]);
    int c = lane * 4;
    const float4 bv = __ldg(reinterpret_cast<const float4*>(bias) + lane);
    const float4 rv = __ldg(reinterpret_cast<const float4*>(res) + (size_t)node * 32 + lane);
    float o0 = fmaxf(fmaf(acc.x, sc, bv.x), 0.f) + rv.x;
    float o1 = fmaxf(fmaf(acc.y, sc, bv.y), 0.f) + rv.y;
    float o2 = fmaxf(fmaf(acc.z, sc, bv.z), 0.f) + rv.z;
    float o3 = fmaxf(fmaf(acc.w, sc, bv.w), 0.f) + rv.w;
    *reinterpret_cast<float4*>(hout + (size_t)node * 128 + c) = make_float4(o0, o1, o2, o3);
    if (aw) {
        const float4 wv = __ldg(reinterpret_cast<const float4*>(awW) + lane);
        float dot = o0 * wv.x + o1 * wv.y + o2 * wv.z + o3 * wv.w;
#pragma unroll
        for (int o = 16; o > 0; o >>= 1) dot += __shfl_xor_sync(0xffffffffu, dot, o);
        if (lane == 0) aw[node] = 1.0f / (1.0f + expf(-(dot + __ldg(&awb[0]))));
    }
}

// ---------------- readout: one block (128 threads) per graph, no atomics ----------------
__global__ void k_readout(const float* __restrict__ h, const float* __restrict__ aw,
                          const int* __restrict__ gptr, float* __restrict__ gf) {
    int b = blockIdx.x;
    int t = threadIdx.x;     // 128 threads = 128 columns
    int beg = __ldg(&gptr[b]), end = __ldg(&gptr[b + 1]);
    float sum = 0.0f, mx = -INFINITY;
    for (int n = beg; n < end; n++) {
        float v = __ldg(&h[(size_t)n * 128 + t]);
        sum = fmaf(__ldg(&aw[n]), v, sum);
        mx = fmaxf(mx, v);
    }
    if (end == beg) mx = 0.0f;
    gf[(size_t)b * 256 + t]       = sum;
    gf[(size_t)b * 256 + 128 + t] = mx;
}

__global__ void k_build_gcat(const float* __restrict__ g, const float* __restrict__ orl,
                             float* __restrict__ gcat, int B, int T1) {
    int i = blockIdx.x * blockDim.x + threadIdx.x;
    int K = 256 + T1;
    if (i >= B * K) return;
    int b = i / K, k = i - b * K;
    gcat[i] = (k < 256) ? g[b * 256 + k] : orl[(size_t)b * T1 + (k - 256)];
}

// ---------------- generic MLP GEMM: C[M,N] = epi(A[M,K] @ W[K,N] + bias) ----------------
// BM=64, BN=64, BK=16; 256 threads, 4x4 per thread; fully bounds-checked.
__global__ void __launch_bounds__(256, 4)
k_gemm_mlp(const float* __restrict__ A, const float* __restrict__ W,
           const float* __restrict__ bias,
           const float* __restrict__ gamma, const float* __restrict__ beta,
           float* __restrict__ C, int M, int N, int K) {
    __shared__ float As[16][68];
    __shared__ float Bs[16][64];
    int t  = threadIdx.x;
    int ty = t >> 4, tx = t & 15;
    int row0 = blockIdx.y * 64;
    int col0 = blockIdx.x * 64;

    float acc[4][4];
#pragma unroll
    for (int j = 0; j < 4; j++)
#pragma unroll
        for (int i = 0; i < 4; i++) acc[j][i] = 0.0f;

    int ktiles = (K + 15) / 16;
    for (int kt = 0; kt < ktiles; kt++) {
#pragma unroll
        for (int i = 0; i < 4; i++) {
            int f = t + i * 256;
            int r = f >> 4, kk = f & 15;
            int grow = row0 + r, gk = kt * 16 + kk;
            As[kk][r] = (grow < M && gk < K) ? A[(size_t)grow * K + gk] : 0.0f;
        }
#pragma unroll
        for (int i = 0; i < 4; i++) {
            int f = t + i * 256;
            int r = f >> 6, c = f & 63;
            int gk = kt * 16 + r, gc = col0 + c;
            Bs[r][c] = (gk < K && gc < N) ? W[(size_t)gk * N + gc] : 0.0f;
        }
        __syncthreads();
#pragma unroll
        for (int k = 0; k < 16; k++) {
            float4 a = *reinterpret_cast<float4*>(&As[k][ty * 4]);
            float4 b = *reinterpret_cast<float4*>(&Bs[k][tx * 4]);
            float av[4] = {a.x, a.y, a.z, a.w};
            float bv[4] = {b.x, b.y, b.z, b.w};
#pragma unroll
            for (int j = 0; j < 4; j++)
#pragma unroll
                for (int i = 0; i < 4; i++)
                    acc[j][i] = fmaf(av[j], bv[i], acc[j][i]);
        }
        __syncthreads();
    }

#pragma unroll
    for (int j = 0; j < 4; j++) {
        int row = row0 + ty * 4 + j;
        if (row >= M) continue;
#pragma unroll
        for (int i = 0; i < 4; i++) {
            int col = col0 + tx * 4 + i;
            if (col >= N) continue;
            float v = acc[j][i] + bias[col];
            if (gamma) {                       // ReLU -> eval BatchNorm
                v = fmaxf(v, 0.0f);
                v = fmaf(gamma[col], v * BN_INV, beta[col]);
            }
            C[(size_t)row * N + col] = v;
        }
    }
}

// ---------------- driver ----------------
extern "C" void kernel_launch(void* const* d_in, const int* in_sizes, int n_in,
                              void* d_out, int out_size) {
    const float* feats  = (const float*)d_in[0];
    const int*   src    = (const int*)  d_in[1];
    const int*   dst    = (const int*)  d_in[2];
    const int*   gid    = (const int*)  d_in[3];
    const float* W1     = (const float*)d_in[4];
    const float* b1     = (const float*)d_in[5];
    const float* resW1  = (const float*)d_in[6];
    const float* resb1  = (const float*)d_in[7];
    const float* W2     = (const float*)d_in[8];
    const float* b2     = (const float*)d_in[9];
    const float* resW2  = (const float*)d_in[10];
    const float* resb2  = (const float*)d_in[11];
    const float* awW    = (const float*)d_in[12];
    const float* awb    = (const float*)d_in[13];
    const float* orW1   = (const float*)d_in[14];
    const float* orb1   = (const float*)d_in[15];
    const float* org    = (const float*)d_in[16];
    const float* orbeta = (const float*)d_in[17];
    const float* orW2   = (const float*)d_in[18];
    const float* orb2   = (const float*)d_in[19];
    const float* scW1   = (const float*)d_in[20];
    const float* scb1   = (const float*)d_in[21];
    const float* scg    = (const float*)d_in[22];
    const float* scbeta = (const float*)d_in[23];
    const float* scW2   = (const float*)d_in[24];
    const float* scb2   = (const float*)d_in[25];

    const int N  = in_sizes[0] / 128;
    const int E  = in_sizes[1];
    const int T1 = in_sizes[19];
    const int T2 = in_sizes[25];
    const int B  = out_size / (T1 + T2);

    float *hw, *res, *h, *on, *inn, *aw, *gf, *z, *gcat;
    int *degs, *degd, *rowptr, *cursor, *csrc, *gcnt, *gptr, *bsums;
    cudaGetSymbolAddress((void**)&hw,     g_hw);
    cudaGetSymbolAddress((void**)&res,    g_res);
    cudaGetSymbolAddress((void**)&h,      g_h);
    cudaGetSymbolAddress((void**)&on,     g_on);
    cudaGetSymbolAddress((void**)&inn,    g_in);
    cudaGetSymbolAddress((void**)&aw,     g_aw);
    cudaGetSymbolAddress((void**)&degs,   g_degs);
    cudaGetSymbolAddress((void**)&degd,   g_degd);
    cudaGetSymbolAddress((void**)&rowptr, g_rowptr);
    cudaGetSymbolAddress((void**)&cursor, g_cursor);
    cudaGetSymbolAddress((void**)&csrc,   g_csrc);
    cudaGetSymbolAddress((void**)&gcnt,   g_gcnt);
    cudaGetSymbolAddress((void**)&gptr,   g_gptr);
    cudaGetSymbolAddress((void**)&bsums,  g_bsums);
    cudaGetSymbolAddress((void**)&gf,     g_gf);
    cudaGetSymbolAddress((void**)&z,      g_z);
    cudaGetSymbolAddress((void**)&gcat,   g_gcat);

    float* out_or = (float*)d_out;
    float* out_sc = (float*)d_out + (size_t)B * T1;

    const int TB = 256;
    dim3 gN((unsigned)((N + TB - 1) / TB));
    dim3 gE((unsigned)((E + TB - 1) / TB));
    dim3 gB((unsigned)((B + TB - 1) / TB));
    dim3 gRows((unsigned)((N + 127) / 128));
    dim3 gWarp((unsigned)((N + 7) / 8));        // 8 warps/block, 1 node/warp

    // degrees, graph histogram, norms
    k_init<<<gN, TB>>>(degs, degd, gcnt, N, B);
    k_count<<<gE, TB>>>(src, dst, E, degs, degd);
    k_hist<<<gN, TB>>>(gid, N, gcnt);
    k_norm<<<gN, TB>>>(degs, degd, on, inn, N);

    // CSR over dst (in-edges)
    {
        int nb = (N + 1023) / 1024;
        k_scan_partial<<<nb, 256>>>(degd, rowptr, bsums, N);
        k_scan_bsums<<<1, 128>>>(bsums, nb);
        k_scan_add<<<gN, TB>>>(rowptr, bsums, N, E);
    }
    k_copy_i<<<gN, TB>>>(rowptr, cursor, N);
    k_fill_csr<<<gE, TB>>>(src, dst, E, cursor, csrc);

    // graph rowptr
    {
        int nb = (B + 1023) / 1024;
        k_scan_partial<<<nb, 256>>>(gcnt, gptr, bsums, B);
        k_scan_bsums<<<1, 128>>>(bsums, nb);
        k_scan_add<<<gB, TB>>>(gptr, bsums, B, N);
    }

    // ---- layer 1 ----
    k_gemm_node<<<gRows, TB>>>(feats, W1, on, nullptr, hw, N, 0);
    k_gemm_node<<<gRows, TB>>>(feats, resW1, nullptr, resb1, res, N, 1);
    k_gather<<<gWarp, TB>>>(hw, rowptr, csrc, inn, b1, res, h,
                            nullptr, nullptr, nullptr, N);

    // ---- layer 2 (atom weights fused into gather epilogue) ----
    k_gemm_node<<<gRows, TB>>>(h, W2, on, nullptr, hw, N, 0);
    k_gemm_node<<<gRows, TB>>>(h, resW2, nullptr, resb2, res, N, 1);
    k_gather<<<gWarp, TB>>>(hw, rowptr, csrc, inn, b2, res, h,
                            aw, awW, awb, N);

    // ---- readout (block per graph) ----
    k_readout<<<B, 128>>>(h, aw, gptr, gf);

    // ---- MLP heads ----
    dim3 gM1((128 + 63) / 64, (B + 63) / 64);
    k_gemm_mlp<<<gM1, TB>>>(gf, orW1, orb1, org, orbeta, z, B, 128, 256);
    dim3 gM2((unsigned)((T1 + 63) / 64), (B + 63) / 64);
    k_gemm_mlp<<<gM2, TB>>>(z, orW2, orb2, nullptr, nullptr, out_or, B, T1, 128);

    int Kc = 256 + T1;
    dim3 gGC((unsigned)((B * Kc + TB - 1) / TB));
    k_build_gcat<<<gGC, TB>>>(gf, out_or, gcat, B, T1);
    k_gemm_mlp<<<gM1, TB>>>(gcat, scW1, scb1, scg, scbeta, z, B, 128, Kc);
    dim3 gM3((unsigned)((T2 + 63) / 64), (B + 63) / 64);
    k_gemm_mlp<<<gM3, TB>>>(z, scW2, scb2, nullptr, nullptr, out_sc, B, T2, 128);
}

// round 13
// speedup vs baseline: 1.0021x; 1.0021x over previous
#include <cuda_runtime.h>
#include <cuda_fp16.h>
#include <math.h>
#include <stdint.h>

// ---------------- static scratch (no allocations allowed) ----------------
#define MAXN 100000
#define MAXB 4096
#define MAXE 3200000

static __device__ __half g_hw [MAXN * 128];   // fp16 message payload
static __device__ float g_res [MAXN * 128];
static __device__ float g_h   [MAXN * 128];
static __device__ float g_on  [MAXN];
static __device__ float g_in  [MAXN];
static __device__ float g_aw  [MAXN];
static __device__ int   g_degs[MAXN];
static __device__ int   g_degd[MAXN];
static __device__ int   g_rowptr[MAXN + 1];
static __device__ int   g_cursor[MAXN];
static __device__ int   g_csrc[MAXE];
static __device__ int   g_gcnt[MAXB];
static __device__ int   g_gptr[MAXB + 1];
static __device__ int   g_bsums[256];
static __device__ float g_gf  [MAXB * 256];
static __device__ float g_z   [MAXB * 128];
static __device__ float g_gcat[MAXB * 832];

#define BN_INV 0.99999500003749971f

// ---------------- init / degree kernels ----------------
__global__ void k_init(int* degs, int* degd, int* gcnt, int N, int B) {
    int i = blockIdx.x * blockDim.x + threadIdx.x;
    if (i < N) { degs[i] = 0; degd[i] = 0; }
    if (i < B) gcnt[i] = 0;
}
__global__ void k_count(const int* __restrict__ src, const int* __restrict__ dst,
                        int E, int* ds, int* dd) {
    int i = blockIdx.x * blockDim.x + threadIdx.x;
    if (i < E) {
        atomicAdd(&ds[src[i]], 1);
        atomicAdd(&dd[dst[i]], 1);
    }
}
__global__ void k_hist(const int* __restrict__ gid, int N, int* cnt) {
    int i = blockIdx.x * blockDim.x + threadIdx.x;
    if (i < N) atomicAdd(&cnt[gid[i]], 1);
}
__global__ void k_norm(const int* __restrict__ ds, const int* __restrict__ dd,
                       float* on, float* inn, int N) {
    int i = blockIdx.x * blockDim.x + threadIdx.x;
    if (i < N) {
        on[i]  = rsqrtf((float)max(ds[i], 1));
        inn[i] = rsqrtf((float)max(dd[i], 1));
    }
}

// ---------------- exclusive scan (3-phase, n <= 128*1024) ----------------
__global__ void k_scan_partial(const int* __restrict__ cnt, int* __restrict__ out,
                               int* __restrict__ bsums, int n) {
    __shared__ int sh[8];
    int base = blockIdx.x * 1024;
    int t = threadIdx.x;           // 256 threads, 4 elems each
    int idx = base + t * 4;
    int v[4], s = 0;
#pragma unroll
    for (int j = 0; j < 4; j++) {
        v[j] = (idx + j < n) ? cnt[idx + j] : 0;
        s += v[j];
    }
    int lane = t & 31, wid = t >> 5;
    int x = s;
#pragma unroll
    for (int o = 1; o < 32; o <<= 1) {
        int y = __shfl_up_sync(0xffffffffu, x, o);
        if (lane >= o) x += y;
    }
    if (lane == 31) sh[wid] = x;
    __syncthreads();
    if (wid == 0 && lane < 8) {
        int w = sh[lane];
#pragma unroll
        for (int o = 1; o < 8; o <<= 1) {
            int y = __shfl_up_sync(0xffu, w, o);
            if (lane >= o) w += y;
        }
        sh[lane] = w;
    }
    __syncthreads();
    int run = (x - s) + (wid > 0 ? sh[wid - 1] : 0);
#pragma unroll
    for (int j = 0; j < 4; j++) {
        if (idx + j < n) out[idx + j] = run;
        run += v[j];
    }
    if (t == 255) bsums[blockIdx.x] = run;   // block total
}
__global__ void k_scan_bsums(int* bsums, int nb) {   // nb <= 128; 128 threads
    __shared__ int sh[4];
    int t = threadIdx.x;
    int v = (t < nb) ? bsums[t] : 0;
    int lane = t & 31, wid = t >> 5;
    int x = v;
#pragma unroll
    for (int o = 1; o < 32; o <<= 1) {
        int y = __shfl_up_sync(0xffffffffu, x, o);
        if (lane >= o) x += y;
    }
    if (lane == 31) sh[wid] = x;
    __syncthreads();
    if (wid == 0 && lane < 4) {
        int w = sh[lane];
#pragma unroll
        for (int o = 1; o < 4; o <<= 1) {
            int y = __shfl_up_sync(0xfu, w, o);
            if (lane >= o) w += y;
        }
        sh[lane] = w;
    }
    __syncthreads();
    int excl = (x - v) + (wid > 0 ? sh[wid - 1] : 0);
    if (t < nb) bsums[t] = excl;
}
// adds block offsets; optionally mirrors result into cursor
__global__ void k_scan_add(int* out, const int* __restrict__ bsums, int n, int total,
                           int* cursor) {
    int i = blockIdx.x * blockDim.x + threadIdx.x;
    if (i < n) {
        int v = out[i] + bsums[i >> 10];
        out[i] = v;
        if (cursor) cursor[i] = v;
    }
    if (i == 0) out[n] = total;
}

__global__ void k_fill_csr(const int* __restrict__ src, const int* __restrict__ dst,
                           int E, int* cursor, int* __restrict__ csrc) {
    int i = blockIdx.x * blockDim.x + threadIdx.x;
    if (i < E) {
        int p = atomicAdd(&cursor[dst[i]], 1);
        csrc[p] = src[i];
    }
}

// ---------------- dual node GEMM ----------------
// hw[M,128](fp16) = (scale ⊙rows A) @ W          (scale applied in epilogue)
// res[M,128]      = relu(A @ resW + resb)
// BM=64, BN=256 (128 W-cols | 128 resW-cols), BK=16; 256 threads (16x16).
__global__ void __launch_bounds__(256, 2)
k_gemm_dual(const float* __restrict__ A, const float* __restrict__ W,
            const float* __restrict__ resW, const float* __restrict__ scale,
            const float* __restrict__ resb,
            __half* __restrict__ hw, float* __restrict__ res, int M) {
    __shared__ float As[16][68];    // [k][m]
    __shared__ float Ws[16][256];   // [k][n]; cols 0..127 = W, 128..255 = resW
    int t  = threadIdx.x;
    int tx = t & 15, ty = t >> 4;
    int row0 = blockIdx.x * 64;

    float acc[4][16];
#pragma unroll
    for (int j = 0; j < 4; j++)
#pragma unroll
        for (int i = 0; i < 16; i++) acc[j][i] = 0.0f;

    for (int kt = 0; kt < 8; kt++) {
        // A tile: 64 rows x 16 k = 256 float4, 1 per thread (transposed store)
        {
            int r = t >> 2, c4 = t & 3;
            int grow = row0 + r;
            float4 v = make_float4(0.f, 0.f, 0.f, 0.f);
            if (grow < M)
                v = *reinterpret_cast<const float4*>(&A[(size_t)grow * 128 + kt * 16 + c4 * 4]);
            As[c4 * 4 + 0][r] = v.x;
            As[c4 * 4 + 1][r] = v.y;
            As[c4 * 4 + 2][r] = v.z;
            As[c4 * 4 + 3][r] = v.w;
        }
        // W tile: 16 k x 256 cols = 1024 float4, 4 per thread
#pragma unroll
        for (int i = 0; i < 4; i++) {
            int f = t + i * 256;
            int kk = f >> 6, c4 = f & 63;
            const float* srcp = (c4 < 32)
                ? &W[(size_t)(kt * 16 + kk) * 128 + c4 * 4]
                : &resW[(size_t)(kt * 16 + kk) * 128 + (c4 - 32) * 4];
            *reinterpret_cast<float4*>(&Ws[kk][c4 * 4]) =
                *reinterpret_cast<const float4*>(srcp);
        }
        __syncthreads();
#pragma unroll
        for (int k = 0; k < 16; k++) {
            float4 Av = *reinterpret_cast<float4*>(&As[k][ty * 4]);
            float am[4] = {Av.x, Av.y, Av.z, Av.w};
            float4 B0 = *reinterpret_cast<float4*>(&Ws[k][tx * 4]);
            float4 B1 = *reinterpret_cast<float4*>(&Ws[k][64 + tx * 4]);
            float4 B2 = *reinterpret_cast<float4*>(&Ws[k][128 + tx * 4]);
            float4 B3 = *reinterpret_cast<float4*>(&Ws[k][192 + tx * 4]);
            float bn[16] = {B0.x, B0.y, B0.z, B0.w, B1.x, B1.y, B1.z, B1.w,
                            B2.x, B2.y, B2.z, B2.w, B3.x, B3.y, B3.z, B3.w};
#pragma unroll
            for (int j = 0; j < 4; j++)
#pragma unroll
                for (int i = 0; i < 16; i++)
                    acc[j][i] = fmaf(am[j], bn[i], acc[j][i]);
        }
        __syncthreads();
    }

    const float4 rb0 = __ldg(reinterpret_cast<const float4*>(&resb[tx * 4]));
    const float4 rb1 = __ldg(reinterpret_cast<const float4*>(&resb[64 + tx * 4]));
#pragma unroll
    for (int j = 0; j < 4; j++) {
        int row = row0 + ty * 4 + j;
        if (row >= M) continue;
        float s = __ldg(&scale[row]);
        // hw columns tx*4..+3 and 64+tx*4..+3, stored fp16 (8B per group of 4)
        {
            __half2 p0 = __floats2half2_rn(acc[j][0] * s, acc[j][1] * s);
            __half2 p1 = __floats2half2_rn(acc[j][2] * s, acc[j][3] * s);
            uint2 u;
            u.x = *reinterpret_cast<unsigned*>(&p0);
            u.y = *reinterpret_cast<unsigned*>(&p1);
            *reinterpret_cast<uint2*>(&hw[(size_t)row * 128 + tx * 4]) = u;
            __half2 p2 = __floats2half2_rn(acc[j][4] * s, acc[j][5] * s);
            __half2 p3 = __floats2half2_rn(acc[j][6] * s, acc[j][7] * s);
            uint2 v;
            v.x = *reinterpret_cast<unsigned*>(&p2);
            v.y = *reinterpret_cast<unsigned*>(&p3);
            *reinterpret_cast<uint2*>(&hw[(size_t)row * 128 + 64 + tx * 4]) = v;
        }
        *reinterpret_cast<float4*>(&res[(size_t)row * 128 + tx * 4]) =
            make_float4(fmaxf(acc[j][8]  + rb0.x, 0.f), fmaxf(acc[j][9]  + rb0.y, 0.f),
                        fmaxf(acc[j][10] + rb0.z, 0.f), fmaxf(acc[j][11] + rb0.w, 0.f));
        *reinterpret_cast<float4*>(&res[(size_t)row * 128 + 64 + tx * 4]) =
            make_float4(fmaxf(acc[j][12] + rb1.x, 0.f), fmaxf(acc[j][13] + rb1.y, 0.f),
                        fmaxf(acc[j][14] + rb1.z, 0.f), fmaxf(acc[j][15] + rb1.w, 0.f));
    }
}

// unpack 4 fp16 (uint2) -> float4
__device__ __forceinline__ float4 h4_to_f4(uint2 u) {
    __half2 h0 = *reinterpret_cast<__half2*>(&u.x);
    __half2 h1 = *reinterpret_cast<__half2*>(&u.y);
    float2 f0 = __half22float2(h0);
    float2 f1 = __half22float2(h1);
    return make_float4(f0.x, f0.y, f1.x, f1.y);
}

// ---------------- CSR gather + finalize (+ optional atom-weight sigmoid) ----------------
// one warp per dst node; lane owns 4 columns (8B fp16 per edge); 8 edges in flight
__global__ void k_gather(const __half* __restrict__ hw, const int* __restrict__ rowptr,
                         const int* __restrict__ csrc, const float* __restrict__ inn,
                         const float* __restrict__ bias, const float* __restrict__ res,
                         float* __restrict__ hout, float* __restrict__ aw,
                         const float* __restrict__ awW, const float* __restrict__ awb, int N) {
    int node = (blockIdx.x * blockDim.x + threadIdx.x) >> 5;
    int lane = threadIdx.x & 31;
    if (node >= N) return;
    int e = __ldg(&rowptr[node]), end = __ldg(&rowptr[node + 1]);
    const uint2* hw8 = reinterpret_cast<const uint2*>(hw);  // 8B = 4 fp16; row = 32 uint2
    float4 a0 = make_float4(0.f, 0.f, 0.f, 0.f), a1 = a0, a2 = a0, a3 = a0;
    for (; e + 8 <= end; e += 8) {
        int s0 = __ldg(&csrc[e]);
        int s1 = __ldg(&csrc[e + 1]);
        int s2 = __ldg(&csrc[e + 2]);
        int s3 = __ldg(&csrc[e + 3]);
        int s4 = __ldg(&csrc[e + 4]);
        int s5 = __ldg(&csrc[e + 5]);
        int s6 = __ldg(&csrc[e + 6]);
        int s7 = __ldg(&csrc[e + 7]);
        uint2 u0 = __ldg(hw8 + (size_t)s0 * 32 + lane);
        uint2 u1 = __ldg(hw8 + (size_t)s1 * 32 + lane);
        uint2 u2 = __ldg(hw8 + (size_t)s2 * 32 + lane);
        uint2 u3 = __ldg(hw8 + (size_t)s3 * 32 + lane);
        uint2 u4 = __ldg(hw8 + (size_t)s4 * 32 + lane);
        uint2 u5 = __ldg(hw8 + (size_t)s5 * 32 + lane);
        uint2 u6 = __ldg(hw8 + (size_t)s6 * 32 + lane);
        uint2 u7 = __ldg(hw8 + (size_t)s7 * 32 + lane);
        float4 v0 = h4_to_f4(u0), v1 = h4_to_f4(u1), v2 = h4_to_f4(u2), v3 = h4_to_f4(u3);
        float4 v4 = h4_to_f4(u4), v5 = h4_to_f4(u5), v6 = h4_to_f4(u6), v7 = h4_to_f4(u7);
        a0.x += v0.x; a0.y += v0.y; a0.z += v0.z; a0.w += v0.w;
        a1.x += v1.x; a1.y += v1.y; a1.z += v1.z; a1.w += v1.w;
        a2.x += v2.x; a2.y += v2.y; a2.z += v2.z; a2.w += v2.w;
        a3.x += v3.x; a3.y += v3.y; a3.z += v3.z; a3.w += v3.w;
        a0.x += v4.x; a0.y += v4.y; a0.z += v4.z; a0.w += v4.w;
        a1.x += v5.x; a1.y += v5.y; a1.z += v5.z; a1.w += v5.w;
        a2.x += v6.x; a2.y += v6.y; a2.z += v6.z; a2.w += v6.w;
        a3.x += v7.x; a3.y += v7.y; a3.z += v7.z; a3.w += v7.w;
    }
    for (; e < end; e++) {
        int s = __ldg(&csrc[e]);
        float4 v = h4_to_f4(__ldg(hw8 + (size_t)s * 32 + lane));
        a0.x += v.x; a0.y += v.y; a0.z += v.z; a0.w += v.w;
    }
    float4 acc = make_float4(a0.x + a1.x + a2.x + a3.x,
                             a0.y + a1.y + a2.y + a3.y,
                             a0.z + a1.z + a2.z + a3.z,
                             a0.w + a1.w + a2.w + a3.w);
    float sc = __ldg(&inn[node]);
    int c = lane * 4;
    const float4 bv = __ldg(reinterpret_cast<const float4*>(bias) + lane);
    const float4 rv = __ldg(reinterpret_cast<const float4*>(res) + (size_t)node * 32 + lane);
    float o0 = fmaxf(fmaf(acc.x, sc, bv.x), 0.f) + rv.x;
    float o1 = fmaxf(fmaf(acc.y, sc, bv.y), 0.f) + rv.y;
    float o2 = fmaxf(fmaf(acc.z, sc, bv.z), 0.f) + rv.z;
    float o3 = fmaxf(fmaf(acc.w, sc, bv.w), 0.f) + rv.w;
    *reinterpret_cast<float4*>(hout + (size_t)node * 128 + c) = make_float4(o0, o1, o2, o3);
    if (aw) {
        const float4 wv = __ldg(reinterpret_cast<const float4*>(awW) + lane);
        float dot = o0 * wv.x + o1 * wv.y + o2 * wv.z + o3 * wv.w;
#pragma unroll
        for (int o = 16; o > 0; o >>= 1) dot += __shfl_xor_sync(0xffffffffu, dot, o);
        if (lane == 0) aw[node] = 1.0f / (1.0f + expf(-(dot + __ldg(&awb[0]))));
    }
}

// ---------------- readout: one block (128 threads) per graph, no atomics ----------------
__global__ void k_readout(const float* __restrict__ h, const float* __restrict__ aw,
                          const int* __restrict__ gptr, float* __restrict__ gf) {
    int b = blockIdx.x;
    int t = threadIdx.x;     // 128 threads = 128 columns
    int beg = __ldg(&gptr[b]), end = __ldg(&gptr[b + 1]);
    float sum = 0.0f, mx = -INFINITY;
    for (int n = beg; n < end; n++) {
        float v = __ldg(&h[(size_t)n * 128 + t]);
        sum = fmaf(__ldg(&aw[n]), v, sum);
        mx = fmaxf(mx, v);
    }
    if (end == beg) mx = 0.0f;
    gf[(size_t)b * 256 + t]       = sum;
    gf[(size_t)b * 256 + 128 + t] = mx;
}

__global__ void k_build_gcat(const float* __restrict__ g, const float* __restrict__ orl,
                             float* __restrict__ gcat, int B, int T1) {
    int i = blockIdx.x * blockDim.x + threadIdx.x;
    int K = 256 + T1;
    if (i >= B * K) return;
    int b = i / K, k = i - b * K;
    gcat[i] = (k < 256) ? g[b * 256 + k] : orl[(size_t)b * T1 + (k - 256)];
}

// ---------------- generic MLP GEMM: C[M,N] = epi(A[M,K] @ W[K,N] + bias) ----------------
// BM=64, BN=64, BK=16; 256 threads, 4x4 per thread; fully bounds-checked.
__global__ void __launch_bounds__(256, 4)
k_gemm_mlp(const float* __restrict__ A, const float* __restrict__ W,
           const float* __restrict__ bias,
           const float* __restrict__ gamma, const float* __restrict__ beta,
           float* __restrict__ C, int M, int N, int K) {
    __shared__ float As[16][68];
    __shared__ float Bs[16][64];
    int t  = threadIdx.x;
    int ty = t >> 4, tx = t & 15;
    int row0 = blockIdx.y * 64;
    int col0 = blockIdx.x * 64;

    float acc[4][4];
#pragma unroll
    for (int j = 0; j < 4; j++)
#pragma unroll
        for (int i = 0; i < 4; i++) acc[j][i] = 0.0f;

    int ktiles = (K + 15) / 16;
    for (int kt = 0; kt < ktiles; kt++) {
#pragma unroll
        for (int i = 0; i < 4; i++) {
            int f = t + i * 256;
            int r = f >> 4, kk = f & 15;
            int grow = row0 + r, gk = kt * 16 + kk;
            As[kk][r] = (grow < M && gk < K) ? A[(size_t)grow * K + gk] : 0.0f;
        }
#pragma unroll
        for (int i = 0; i < 4; i++) {
            int f = t + i * 256;
            int r = f >> 6, c = f & 63;
            int gk = kt * 16 + r, gc = col0 + c;
            Bs[r][c] = (gk < K && gc < N) ? W[(size_t)gk * N + gc] : 0.0f;
        }
        __syncthreads();
#pragma unroll
        for (int k = 0; k < 16; k++) {
            float4 a = *reinterpret_cast<float4*>(&As[k][ty * 4]);
            float4 b = *reinterpret_cast<float4*>(&Bs[k][tx * 4]);
            float av[4] = {a.x, a.y, a.z, a.w};
            float bv[4] = {b.x, b.y, b.z, b.w};
#pragma unroll
            for (int j = 0; j < 4; j++)
#pragma unroll
                for (int i = 0; i < 4; i++)
                    acc[j][i] = fmaf(av[j], bv[i], acc[j][i]);
        }
        __syncthreads();
    }

#pragma unroll
    for (int j = 0; j < 4; j++) {
        int row = row0 + ty * 4 + j;
        if (row >= M) continue;
#pragma unroll
        for (int i = 0; i < 4; i++) {
            int col = col0 + tx * 4 + i;
            if (col >= N) continue;
            float v = acc[j][i] + bias[col];
            if (gamma) {                       // ReLU -> eval BatchNorm
                v = fmaxf(v, 0.0f);
                v = fmaf(gamma[col], v * BN_INV, beta[col]);
            }
            C[(size_t)row * N + col] = v;
        }
    }
}

// ---------------- driver ----------------
extern "C" void kernel_launch(void* const* d_in, const int* in_sizes, int n_in,
                              void* d_out, int out_size) {
    const float* feats  = (const float*)d_in[0];
    const int*   src    = (const int*)  d_in[1];
    const int*   dst    = (const int*)  d_in[2];
    const int*   gid    = (const int*)  d_in[3];
    const float* W1     = (const float*)d_in[4];
    const float* b1     = (const float*)d_in[5];
    const float* resW1  = (const float*)d_in[6];
    const float* resb1  = (const float*)d_in[7];
    const float* W2     = (const float*)d_in[8];
    const float* b2     = (const float*)d_in[9];
    const float* resW2  = (const float*)d_in[10];
    const float* resb2  = (const float*)d_in[11];
    const float* awW    = (const float*)d_in[12];
    const float* awb    = (const float*)d_in[13];
    const float* orW1   = (const float*)d_in[14];
    const float* orb1   = (const float*)d_in[15];
    const float* org    = (const float*)d_in[16];
    const float* orbeta = (const float*)d_in[17];
    const float* orW2   = (const float*)d_in[18];
    const float* orb2   = (const float*)d_in[19];
    const float* scW1   = (const float*)d_in[20];
    const float* scb1   = (const float*)d_in[21];
    const float* scg    = (const float*)d_in[22];
    const float* scbeta = (const float*)d_in[23];
    const float* scW2   = (const float*)d_in[24];
    const float* scb2   = (const float*)d_in[25];

    const int N  = in_sizes[0] / 128;
    const int E  = in_sizes[1];
    const int T1 = in_sizes[19];
    const int T2 = in_sizes[25];
    const int B  = out_size / (T1 + T2);

    __half* hw;
    float *res, *h, *on, *inn, *aw, *gf, *z, *gcat;
    int *degs, *degd, *rowptr, *cursor, *csrc, *gcnt, *gptr, *bsums;
    cudaGetSymbolAddress((void**)&hw,     g_hw);
    cudaGetSymbolAddress((void**)&res,    g_res);
    cudaGetSymbolAddress((void**)&h,      g_h);
    cudaGetSymbolAddress((void**)&on,     g_on);
    cudaGetSymbolAddress((void**)&inn,    g_in);
    cudaGetSymbolAddress((void**)&aw,     g_aw);
    cudaGetSymbolAddress((void**)&degs,   g_degs);
    cudaGetSymbolAddress((void**)&degd,   g_degd);
    cudaGetSymbolAddress((void**)&rowptr, g_rowptr);
    cudaGetSymbolAddress((void**)&cursor, g_cursor);
    cudaGetSymbolAddress((void**)&csrc,   g_csrc);
    cudaGetSymbolAddress((void**)&gcnt,   g_gcnt);
    cudaGetSymbolAddress((void**)&gptr,   g_gptr);
    cudaGetSymbolAddress((void**)&bsums,  g_bsums);
    cudaGetSymbolAddress((void**)&gf,     g_gf);
    cudaGetSymbolAddress((void**)&z,      g_z);
    cudaGetSymbolAddress((void**)&gcat,   g_gcat);

    float* out_or = (float*)d_out;
    float* out_sc = (float*)d_out + (size_t)B * T1;

    const int TB = 256;
    dim3 gN((unsigned)((N + TB - 1) / TB));
    dim3 gE((unsigned)((E + TB - 1) / TB));
    dim3 gB((unsigned)((B + TB - 1) / TB));
    dim3 gRows64((unsigned)((N + 63) / 64));
    dim3 gWarp((unsigned)((N + 7) / 8));        // 8 warps/block, 1 node/warp

    // degrees, graph histogram, norms
    k_init<<<gN, TB>>>(degs, degd, gcnt, N, B);
    k_count<<<gE, TB>>>(src, dst, E, degs, degd);
    k_hist<<<gN, TB>>>(gid, N, gcnt);
    k_norm<<<gN, TB>>>(degs, degd, on, inn, N);

    // CSR over dst (in-edges); cursor mirrored in the add phase
    {
        int nb = (N + 1023) / 1024;
        k_scan_partial<<<nb, 256>>>(degd, rowptr, bsums, N);
        k_scan_bsums<<<1, 128>>>(bsums, nb);
        k_scan_add<<<gN, TB>>>(rowptr, bsums, N, E, cursor);
    }
    k_fill_csr<<<gE, TB>>>(src, dst, E, cursor, csrc);

    // graph rowptr
    {
        int nb = (B + 1023) / 1024;
        k_scan_partial<<<nb, 256>>>(gcnt, gptr, bsums, B);
        k_scan_bsums<<<1, 128>>>(bsums, nb);
        k_scan_add<<<gB, TB>>>(gptr, bsums, B, N, nullptr);
    }

    // ---- layer 1 ----
    k_gemm_dual<<<gRows64, TB>>>(feats, W1, resW1, on, resb1, hw, res, N);
    k_gather<<<gWarp, TB>>>(hw, rowptr, csrc, inn, b1, res, h,
                            nullptr, nullptr, nullptr, N);

    // ---- layer 2 (atom weights fused into gather epilogue) ----
    k_gemm_dual<<<gRows64, TB>>>(h, W2, resW2, on, resb2, hw, res, N);
    k_gather<<<gWarp, TB>>>(hw, rowptr, csrc, inn, b2, res, h,
                            aw, awW, awb, N);

    // ---- readout (block per graph) ----
    k_readout<<<B, 128>>>(h, aw, gptr, gf);

    // ---- MLP heads ----
    dim3 gM1((128 + 63) / 64, (B + 63) / 64);
    k_gemm_mlp<<<gM1, TB>>>(gf, orW1, orb1, org, orbeta, z, B, 128, 256);
    dim3 gM2((unsigned)((T1 + 63) / 64), (B + 63) / 64);
    k_gemm_mlp<<<gM2, TB>>>(z, orW2, orb2, nullptr, nullptr, out_or, B, T1, 128);

    int Kc = 256 + T1;
    dim3 gGC((unsigned)((B * Kc + TB - 1) / TB));
    k_build_gcat<<<gGC, TB>>>(gf, out_or, gcat, B, T1);
    k_gemm_mlp<<<gM1, TB>>>(gcat, scW1, scb1, scg, scbeta, z, B, 128, Kc);
    dim3 gM3((unsigned)((T2 + 63) / 64), (B + 63) / 64);
    k_gemm_mlp<<<gM3, TB>>>(z, scW2, scb2, nullptr, nullptr, out_sc, B, T2, 128);
}